// round 13
// baseline (speedup 1.0000x reference)
#include <cuda_runtime.h>
#include <cuda_fp16.h>
#include <cstdint>

#define ND 64
#define THREADS 320
#define NWARP 10
#define TILE_R 320           // rows per CTA tile (10 warps x m32)

// ---- smem layout (bytes) ----
#define BF_OFF   0                    // uint4 [3 l][12 j][4 p][32 lane] = 73728
#define BIAS_OFF 73728                // 192 floats = 768
#define EPI_OFF  74496                // 10 warps * 32*68 floats = 87040 (scr overlaps)
#define SMEM_BYTES (74496 + 87040)    // 161536

__device__ __forceinline__ uint32_t pk_h(float v0, float v1) {
    __half2 h = __floats2half2_rn(v0, v1);      // single cvt.rn.f16x2.f32
    return *reinterpret_cast<uint32_t*>(&h);
}

__device__ __forceinline__ void mma4(float* c, const uint32_t* a, uint32_t b0, uint32_t b1) {
    asm volatile(
        "mma.sync.aligned.m16n8k16.row.col.f32.f16.f16.f32 "
        "{%0,%1,%2,%3}, {%4,%5,%6,%7}, {%8,%9}, {%0,%1,%2,%3};"
        : "+f"(c[0]), "+f"(c[1]), "+f"(c[2]), "+f"(c[3])
        : "r"(a[0]), "r"(a[1]), "r"(a[2]), "r"(a[3]), "r"(b0), "r"(b1));
}

__global__ __launch_bounds__(THREADS, 1)
void dijet_mma(const float* __restrict__ x, const float* __restrict__ dd,
               const float* __restrict__ W1, const float* __restrict__ b1,
               const float* __restrict__ W2, const float* __restrict__ b2,
               const float* __restrict__ W3, const float* __restrict__ b3,
               float* __restrict__ out, int n) {
    extern __shared__ char smem[];
    uint4*  Bfr  = (uint4*)(smem + BF_OFF);
    float*  bias = (float*)(smem + BIAS_OFF);
    float*  scr  = (float*)(smem + EPI_OFF);     // staging bounce, overlapped with eb

    const int tid  = threadIdx.x;
    const int w    = tid >> 5;
    const int lane = tid & 31;
    const int g    = lane >> 2;     // row-in-frag 0..7
    const int c    = lane & 3;      // k/n sub-index

    float* eb = (float*)(smem + EPI_OFF) + w * (32 * 68);

    if (tid < 64) { bias[tid] = b1[tid]; bias[64 + tid] = b2[tid]; bias[128 + tid] = b3[tid]; }

    // ==== stage weights once: fp32 [o][i][k] -> single-fp16 fragments ====
    {
        const float* Wg[3] = {W1, W2, W3};
        for (int l = 0; l < 3; ++l) {
            for (int oh = 0; oh < 2; ++oh) {
                __syncthreads();
                const float4* src = (const float4*)(Wg[l] + oh * 32 * 192);
                float4* dst = (float4*)scr;
                for (int i4 = tid; i4 < 1536; i4 += THREADS) dst[i4] = src[i4];
                __syncthreads();
                for (int cmb = w; cmb < 24; cmb += NWARP) {
                    int j = cmb >> 1, pp = cmb & 1, p = oh * 2 + pp;
                    int nl0 = pp * 16 + g, nl1 = nl0 + 8;
                    int k0 = j * 16 + 2 * c;
                    int blk = k0 >> 6, i0 = k0 & 63;
                    const float* s0p = scr + nl0 * 192 + blk;
                    const float* s1p = scr + nl1 * 192 + blk;
                    uint32_t h0 = pk_h(s0p[i0 * 3],       s0p[(i0 + 1) * 3]);
                    uint32_t h1 = pk_h(s0p[(i0 + 8) * 3], s0p[(i0 + 9) * 3]);
                    uint32_t h2 = pk_h(s1p[i0 * 3],       s1p[(i0 + 1) * 3]);
                    uint32_t h3 = pk_h(s1p[(i0 + 8) * 3], s1p[(i0 + 9) * 3]);
                    Bfr[((l * 12 + j) * 4 + p) * 32 + lane] = make_uint4(h0, h1, h2, h3);
                }
            }
        }
        __syncthreads();   // last barrier: Bfr/bias read-only from here on
    }

    const long rmax   = (long)n * 6;
    const int  ntiles = (int)((rmax + TILE_R - 1) / TILE_R);

    for (int tile = blockIdx.x; tile < ntiles; tile += gridDim.x) {
        const long base = (long)tile * TILE_R;
        const long row0 = base + w * 32;           // this warp's first row (m32)

        uint32_t Ahx[2][8][4], Ahd[2][4][4];
        int sa0h[2], sl0h[2], sa1h[2], sl1h[2];
        bool v0h[2], v1h[2];

        // ==== direct gmem gather -> A fragments, two m16 halves ====
#pragma unroll
        for (int h = 0; h < 2; ++h) {
            const long r0 = row0 + 16 * h + g;
            const long r1 = r0 + 8;
            const bool v0 = r0 < rmax, v1 = r1 < rmax;
            const int  sa0 = (int)(r0 / 6), sl0 = (int)(r0 - (long)sa0 * 6);
            const int  sa1 = (int)(r1 / 6), sl1 = (int)(r1 - (long)sa1 * 6);
            sa0h[h] = sa0; sl0h[h] = sl0; sa1h[h] = sa1; sl1h[h] = sl1;
            v0h[h] = v0; v1h[h] = v1;

            const float* px0 = x + (size_t)sa0 * 768 + 2 * sl0;
            const float* px1 = x + (size_t)sa1 * 768 + 2 * sl1;
            const float2 z2 = make_float2(0.f, 0.f);
#pragma unroll
            for (int j = 0; j < 4; ++j) {
                const int i0 = j * 16 + 2 * c;
                float2 p00 = v0 ? __ldg((const float2*)(px0 + i0 * 12))       : z2;
                float2 p01 = v0 ? __ldg((const float2*)(px0 + (i0 + 1) * 12)) : z2;
                float2 p02 = v0 ? __ldg((const float2*)(px0 + (i0 + 8) * 12)) : z2;
                float2 p03 = v0 ? __ldg((const float2*)(px0 + (i0 + 9) * 12)) : z2;
                float2 p10 = v1 ? __ldg((const float2*)(px1 + i0 * 12))       : z2;
                float2 p11 = v1 ? __ldg((const float2*)(px1 + (i0 + 1) * 12)) : z2;
                float2 p12 = v1 ? __ldg((const float2*)(px1 + (i0 + 8) * 12)) : z2;
                float2 p13 = v1 ? __ldg((const float2*)(px1 + (i0 + 9) * 12)) : z2;
                Ahx[h][j][0]     = pk_h(p00.x, p01.x);
                Ahx[h][j][1]     = pk_h(p10.x, p11.x);
                Ahx[h][j][2]     = pk_h(p02.x, p03.x);
                Ahx[h][j][3]     = pk_h(p12.x, p13.x);
                Ahx[h][j + 4][0] = pk_h(p00.y, p01.y);
                Ahx[h][j + 4][1] = pk_h(p10.y, p11.y);
                Ahx[h][j + 4][2] = pk_h(p02.y, p03.y);
                Ahx[h][j + 4][3] = pk_h(p12.y, p13.y);
            }
            const float* d0p = dd + (size_t)sa0 * 384 + sl0;
            const float* d1p = dd + (size_t)sa1 * 384 + sl1;
#pragma unroll
            for (int jd = 0; jd < 4; ++jd) {
                const int i0 = jd * 16 + 2 * c;
                float e00 = v0 ? __ldg(d0p + i0 * 6)       : 0.f;
                float e01 = v0 ? __ldg(d0p + (i0 + 1) * 6) : 0.f;
                float e02 = v0 ? __ldg(d0p + (i0 + 8) * 6) : 0.f;
                float e03 = v0 ? __ldg(d0p + (i0 + 9) * 6) : 0.f;
                float e10 = v1 ? __ldg(d1p + i0 * 6)       : 0.f;
                float e11 = v1 ? __ldg(d1p + (i0 + 1) * 6) : 0.f;
                float e12 = v1 ? __ldg(d1p + (i0 + 8) * 6) : 0.f;
                float e13 = v1 ? __ldg(d1p + (i0 + 9) * 6) : 0.f;
                Ahd[h][jd][0] = pk_h(e00, e01);
                Ahd[h][jd][1] = pk_h(e10, e11);
                Ahd[h][jd][2] = pk_h(e02, e03);
                Ahd[h][jd][3] = pk_h(e12, e13);
            }
        }

        float acc[2][8][4];
#pragma unroll
        for (int h = 0; h < 2; ++h)
#pragma unroll
            for (int nt = 0; nt < 8; ++nt)
#pragma unroll
                for (int e = 0; e < 4; ++e) acc[h][nt][e] = 0.f;

        // ==== 3 chained layers: each B fragment feeds BOTH m16 halves ====
#pragma unroll
        for (int l = 0; l < 3; ++l) {
#pragma unroll
            for (int j = 0; j < 8; ++j) {
                const uint4* bp = Bfr + ((l * 12 + j) * 4) * 32 + lane;
#pragma unroll
                for (int p = 0; p < 4; ++p) {
                    uint4 bh = bp[p * 32];
#pragma unroll
                    for (int h = 0; h < 2; ++h) {
                        mma4(acc[h][2 * p],     Ahx[h][j], bh.x, bh.y);
                        mma4(acc[h][2 * p + 1], Ahx[h][j], bh.z, bh.w);
                    }
                }
            }
#pragma unroll
            for (int jd = 0; jd < 4; ++jd) {
                const uint4* bp = Bfr + ((l * 12 + 8 + jd) * 4) * 32 + lane;
#pragma unroll
                for (int p = 0; p < 4; ++p) {
                    uint4 bh = bp[p * 32];
#pragma unroll
                    for (int h = 0; h < 2; ++h) {
                        mma4(acc[h][2 * p],     Ahd[h][jd], bh.x, bh.y);
                        mma4(acc[h][2 * p + 1], Ahd[h][jd], bh.z, bh.w);
                    }
                }
            }
            if (l < 2) {
                // D -> next-layer d fragments, register-local (o dim == next k dim)
#pragma unroll
                for (int h = 0; h < 2; ++h)
#pragma unroll
                    for (int jd = 0; jd < 4; ++jd) {
                        const int o0 = jd * 16 + 2 * c;
                        float bb0 = bias[l * 64 + o0],     bb1 = bias[l * 64 + o0 + 1];
                        float bb8 = bias[l * 64 + o0 + 8], bb9 = bias[l * 64 + o0 + 9];
                        Ahd[h][jd][0] = pk_h(fmaxf(acc[h][2 * jd][0] + bb0, 0.f),
                                             fmaxf(acc[h][2 * jd][1] + bb1, 0.f));
                        Ahd[h][jd][1] = pk_h(fmaxf(acc[h][2 * jd][2] + bb0, 0.f),
                                             fmaxf(acc[h][2 * jd][3] + bb1, 0.f));
                        Ahd[h][jd][2] = pk_h(fmaxf(acc[h][2 * jd + 1][0] + bb8, 0.f),
                                             fmaxf(acc[h][2 * jd + 1][1] + bb9, 0.f));
                        Ahd[h][jd][3] = pk_h(fmaxf(acc[h][2 * jd + 1][2] + bb8, 0.f),
                                             fmaxf(acc[h][2 * jd + 1][3] + bb9, 0.f));
#pragma unroll
                        for (int e = 0; e < 4; ++e) {
                            acc[h][2 * jd][e] = 0.f;
                            acc[h][2 * jd + 1][e] = 0.f;
                        }
                    }
            }
        }

        // ==== epilogue: acc+b3 -> warp smem transpose (32 rows) -> relu(+d1) -> gmem ====
        {
#pragma unroll
            for (int h = 0; h < 2; ++h)
#pragma unroll
                for (int nt = 0; nt < 8; ++nt) {
                    const int o0 = nt * 8 + 2 * c;
                    const float bb0 = bias[128 + o0], bb1 = bias[128 + o0 + 1];
                    eb[(16 * h + g) * 68 + o0]           = acc[h][nt][0] + bb0;
                    eb[(16 * h + g) * 68 + o0 + 1]       = acc[h][nt][1] + bb1;
                    eb[(16 * h + g + 8) * 68 + o0]       = acc[h][nt][2] + bb0;
                    eb[(16 * h + g + 8) * 68 + o0 + 1]   = acc[h][nt][3] + bb1;
                }
            __syncwarp();

            const int saA = (int)(row0 / 6);
            const int saB = (int)((row0 + 31) / 6);
            for (int sa = saA; sa <= saB; ++sa) {
                if (sa >= n) break;
                const int mb = (int)((long)sa * 6 - row0);   // row index of slot 0
                if (mb >= 0 && mb + 6 <= 32) {
                    // full sample: coalesced float4 path
                    const float* ddp = dd + (size_t)sa * 384;
                    float*       op  = out + (size_t)sa * 384;
#pragma unroll
                    for (int it = 0; it < 3; ++it) {
                        const int f = (it * 32 + lane) * 4;
                        float4 dv = __ldg((const float4*)(ddp + f));
                        float r[4];
#pragma unroll
                        for (int e = 0; e < 4; ++e) {
                            const int fe = f + e;
                            const int o  = fe / 6;
                            const int sl = fe - o * 6;
                            r[e] = eb[(mb + sl) * 68 + o];
                        }
                        float4 ov;
                        ov.x = fmaxf(r[0] + dv.x, 0.f);
                        ov.y = fmaxf(r[1] + dv.y, 0.f);
                        ov.z = fmaxf(r[2] + dv.z, 0.f);
                        ov.w = fmaxf(r[3] + dv.w, 0.f);
                        *(float4*)(op + f) = ov;
                    }
                } else {
                    // boundary sample: scalar path
#pragma unroll
                    for (int sl = 0; sl < 6; ++sl) {
                        const int m = mb + sl;
                        if (m < 0 || m >= 32) continue;
                        if (row0 + m >= rmax) continue;
#pragma unroll
                        for (int h2 = 0; h2 < 2; ++h2) {
                            const int o = lane + 32 * h2;
                            const size_t a = (size_t)sa * 384 + (size_t)o * 6 + sl;
                            out[a] = fmaxf(eb[m * 68 + o] + dd[a], 0.f);
                        }
                    }
                }
            }
            __syncwarp();   // eb reused next tile
        }
    }
}

extern "C" void kernel_launch(void* const* d_in, const int* in_sizes, int n_in,
                              void* d_out, int out_size) {
    const float* x  = (const float*)d_in[0];
    const float* dd = (const float*)d_in[1];
    const float* W1 = (const float*)d_in[2];
    const float* b1 = (const float*)d_in[3];
    const float* W2 = (const float*)d_in[4];
    const float* b2 = (const float*)d_in[5];
    const float* W3 = (const float*)d_in[6];
    const float* b3 = (const float*)d_in[7];
    float* out = (float*)d_out;

    const int n = in_sizes[0] / (ND * 12);

    int sms = 148;
    cudaDeviceGetAttribute(&sms, cudaDevAttrMultiProcessorCount, 0);
    cudaFuncSetAttribute(dijet_mma, cudaFuncAttributeMaxDynamicSharedMemorySize, SMEM_BYTES);

    dijet_mma<<<sms, THREADS, SMEM_BYTES>>>(x, dd, W1, b1, W2, b2, W3, b3, out, n);
}

// round 14
// speedup vs baseline: 1.1145x; 1.1145x over previous
#include <cuda_runtime.h>
#include <cuda_fp16.h>
#include <cstdint>

#define ND 64
#define THREADS 256
#define NWARP 8
#define TILE_R 128           // rows per CTA tile (8 warps x m16), 2 CTAs/SM

// ---- smem layout (bytes) ----
#define BF_OFF   0                    // uint4 [3 l][12 j][4 p][32 lane] = 73728
#define BIAS_OFF 73728                // 192 floats = 768
#define EPI_OFF  74496                // 8 warps * 16*68 floats = 34816 (scr overlaps)
#define SMEM_BYTES (74496 + 34816)    // 109312  (x2 CTAs = 218624 <= 228KB)

__device__ __forceinline__ uint32_t pk_h(float v0, float v1) {
    __half2 h = __floats2half2_rn(v0, v1);      // single cvt, same rn rounding
    return *reinterpret_cast<uint32_t*>(&h);
}

__device__ __forceinline__ void mma4(float* c, const uint32_t* a, uint32_t b0, uint32_t b1) {
    asm volatile(
        "mma.sync.aligned.m16n8k16.row.col.f32.f16.f16.f32 "
        "{%0,%1,%2,%3}, {%4,%5,%6,%7}, {%8,%9}, {%0,%1,%2,%3};"
        : "+f"(c[0]), "+f"(c[1]), "+f"(c[2]), "+f"(c[3])
        : "r"(a[0]), "r"(a[1]), "r"(a[2]), "r"(a[3]), "r"(b0), "r"(b1));
}

__global__ __launch_bounds__(THREADS, 2)
void dijet_mma(const float* __restrict__ x, const float* __restrict__ dd,
               const float* __restrict__ W1, const float* __restrict__ b1,
               const float* __restrict__ W2, const float* __restrict__ b2,
               const float* __restrict__ W3, const float* __restrict__ b3,
               float* __restrict__ out, int n) {
    extern __shared__ char smem[];
    uint4*  Bfr  = (uint4*)(smem + BF_OFF);
    float*  bias = (float*)(smem + BIAS_OFF);
    float*  scr  = (float*)(smem + EPI_OFF);     // staging bounce, overlapped with eb

    const int tid  = threadIdx.x;
    const int w    = tid >> 5;
    const int lane = tid & 31;
    const int g    = lane >> 2;     // row-in-frag 0..7
    const int c    = lane & 3;      // k/n sub-index

    float* eb = (float*)(smem + EPI_OFF) + w * (16 * 68);

    if (tid < 64) { bias[tid] = b1[tid]; bias[64 + tid] = b2[tid]; bias[128 + tid] = b3[tid]; }

    // ==== stage weights once: fp32 [o][i][k] -> single-fp16 fragments ====
    {
        const float* Wg[3] = {W1, W2, W3};
        for (int l = 0; l < 3; ++l) {
            for (int oh = 0; oh < 2; ++oh) {
                __syncthreads();
                const float4* src = (const float4*)(Wg[l] + oh * 32 * 192);
                float4* dst = (float4*)scr;
                for (int i4 = tid; i4 < 1536; i4 += THREADS) dst[i4] = src[i4];
                __syncthreads();
                for (int cmb = w; cmb < 24; cmb += NWARP) {
                    int j = cmb >> 1, pp = cmb & 1, p = oh * 2 + pp;
                    int nl0 = pp * 16 + g, nl1 = nl0 + 8;
                    int k0 = j * 16 + 2 * c;
                    int blk = k0 >> 6, i0 = k0 & 63;
                    const float* s0p = scr + nl0 * 192 + blk;
                    const float* s1p = scr + nl1 * 192 + blk;
                    uint32_t h0 = pk_h(s0p[i0 * 3],       s0p[(i0 + 1) * 3]);
                    uint32_t h1 = pk_h(s0p[(i0 + 8) * 3], s0p[(i0 + 9) * 3]);
                    uint32_t h2 = pk_h(s1p[i0 * 3],       s1p[(i0 + 1) * 3]);
                    uint32_t h3 = pk_h(s1p[(i0 + 8) * 3], s1p[(i0 + 9) * 3]);
                    Bfr[((l * 12 + j) * 4 + p) * 32 + lane] = make_uint4(h0, h1, h2, h3);
                }
            }
        }
        __syncthreads();   // last barrier: Bfr/bias read-only from here on
    }

    const long rmax   = (long)n * 6;
    const int  ntiles = (int)((rmax + TILE_R - 1) / TILE_R);

    for (int tile = blockIdx.x; tile < ntiles; tile += gridDim.x) {
        const long base = (long)tile * TILE_R;
        const long row0 = base + w * 16;           // this warp's first row

        const long r0 = row0 + g;
        const long r1 = r0 + 8;
        const bool v0 = r0 < rmax, v1 = r1 < rmax;
        const int  sa0 = (int)(r0 / 6), sl0 = (int)(r0 - (long)sa0 * 6);
        const int  sa1 = (int)(r1 / 6), sl1 = (int)(r1 - (long)sa1 * 6);

        uint32_t Ahx[8][4], Ahd[4][4];

        // ==== direct gmem gather -> A fragments (all 1-term fp16) ====
        {
            const float* px0 = x + (size_t)sa0 * 768 + 2 * sl0;
            const float* px1 = x + (size_t)sa1 * 768 + 2 * sl1;
            const float2 z2 = make_float2(0.f, 0.f);
#pragma unroll
            for (int j = 0; j < 4; ++j) {
                const int i0 = j * 16 + 2 * c;
                float2 p00 = v0 ? __ldg((const float2*)(px0 + i0 * 12))       : z2;
                float2 p01 = v0 ? __ldg((const float2*)(px0 + (i0 + 1) * 12)) : z2;
                float2 p02 = v0 ? __ldg((const float2*)(px0 + (i0 + 8) * 12)) : z2;
                float2 p03 = v0 ? __ldg((const float2*)(px0 + (i0 + 9) * 12)) : z2;
                float2 p10 = v1 ? __ldg((const float2*)(px1 + i0 * 12))       : z2;
                float2 p11 = v1 ? __ldg((const float2*)(px1 + (i0 + 1) * 12)) : z2;
                float2 p12 = v1 ? __ldg((const float2*)(px1 + (i0 + 8) * 12)) : z2;
                float2 p13 = v1 ? __ldg((const float2*)(px1 + (i0 + 9) * 12)) : z2;
                Ahx[j][0]     = pk_h(p00.x, p01.x);
                Ahx[j][1]     = pk_h(p10.x, p11.x);
                Ahx[j][2]     = pk_h(p02.x, p03.x);
                Ahx[j][3]     = pk_h(p12.x, p13.x);
                Ahx[j + 4][0] = pk_h(p00.y, p01.y);
                Ahx[j + 4][1] = pk_h(p10.y, p11.y);
                Ahx[j + 4][2] = pk_h(p02.y, p03.y);
                Ahx[j + 4][3] = pk_h(p12.y, p13.y);
            }
            const float* d0p = dd + (size_t)sa0 * 384 + sl0;
            const float* d1p = dd + (size_t)sa1 * 384 + sl1;
#pragma unroll
            for (int jd = 0; jd < 4; ++jd) {
                const int i0 = jd * 16 + 2 * c;
                float e00 = v0 ? __ldg(d0p + i0 * 6)       : 0.f;
                float e01 = v0 ? __ldg(d0p + (i0 + 1) * 6) : 0.f;
                float e02 = v0 ? __ldg(d0p + (i0 + 8) * 6) : 0.f;
                float e03 = v0 ? __ldg(d0p + (i0 + 9) * 6) : 0.f;
                float e10 = v1 ? __ldg(d1p + i0 * 6)       : 0.f;
                float e11 = v1 ? __ldg(d1p + (i0 + 1) * 6) : 0.f;
                float e12 = v1 ? __ldg(d1p + (i0 + 8) * 6) : 0.f;
                float e13 = v1 ? __ldg(d1p + (i0 + 9) * 6) : 0.f;
                Ahd[jd][0] = pk_h(e00, e01);
                Ahd[jd][1] = pk_h(e10, e11);
                Ahd[jd][2] = pk_h(e02, e03);
                Ahd[jd][3] = pk_h(e12, e13);
            }
        }

        float acc[8][4];
#pragma unroll
        for (int nt = 0; nt < 8; ++nt)
#pragma unroll
            for (int e = 0; e < 4; ++e) acc[nt][e] = 0.f;

        // ==== 3 chained layers: all 1-term fp16 ====
#pragma unroll
        for (int l = 0; l < 3; ++l) {
#pragma unroll
            for (int j = 0; j < 8; ++j) {
                const uint4* bp = Bfr + ((l * 12 + j) * 4) * 32 + lane;
#pragma unroll
                for (int p = 0; p < 4; ++p) {
                    uint4 bh = bp[p * 32];
                    mma4(acc[2 * p],     Ahx[j], bh.x, bh.y);
                    mma4(acc[2 * p + 1], Ahx[j], bh.z, bh.w);
                }
            }
#pragma unroll
            for (int jd = 0; jd < 4; ++jd) {
                const uint4* bp = Bfr + ((l * 12 + 8 + jd) * 4) * 32 + lane;
#pragma unroll
                for (int p = 0; p < 4; ++p) {
                    uint4 bh = bp[p * 32];
                    mma4(acc[2 * p],     Ahd[jd], bh.x, bh.y);
                    mma4(acc[2 * p + 1], Ahd[jd], bh.z, bh.w);
                }
            }
            if (l < 2) {
                // D -> next-layer d fragments, register-local (o dim == next k dim)
#pragma unroll
                for (int jd = 0; jd < 4; ++jd) {
                    const int o0 = jd * 16 + 2 * c;
                    float bb0 = bias[l * 64 + o0],     bb1 = bias[l * 64 + o0 + 1];
                    float bb8 = bias[l * 64 + o0 + 8], bb9 = bias[l * 64 + o0 + 9];
                    Ahd[jd][0] = pk_h(fmaxf(acc[2 * jd][0] + bb0, 0.f),
                                      fmaxf(acc[2 * jd][1] + bb1, 0.f));
                    Ahd[jd][1] = pk_h(fmaxf(acc[2 * jd][2] + bb0, 0.f),
                                      fmaxf(acc[2 * jd][3] + bb1, 0.f));
                    Ahd[jd][2] = pk_h(fmaxf(acc[2 * jd + 1][0] + bb8, 0.f),
                                      fmaxf(acc[2 * jd + 1][1] + bb9, 0.f));
                    Ahd[jd][3] = pk_h(fmaxf(acc[2 * jd + 1][2] + bb8, 0.f),
                                      fmaxf(acc[2 * jd + 1][3] + bb9, 0.f));
#pragma unroll
                    for (int e = 0; e < 4; ++e) {
                        acc[2 * jd][e] = 0.f;
                        acc[2 * jd + 1][e] = 0.f;
                    }
                }
            }
        }

        // ==== epilogue: acc+b3 -> warp smem transpose -> relu(+d1) -> gmem ====
        {
#pragma unroll
            for (int nt = 0; nt < 8; ++nt) {
                const int o0 = nt * 8 + 2 * c;
                const float bb0 = bias[128 + o0], bb1 = bias[128 + o0 + 1];
                eb[g * 68 + o0]           = acc[nt][0] + bb0;
                eb[g * 68 + o0 + 1]       = acc[nt][1] + bb1;
                eb[(g + 8) * 68 + o0]     = acc[nt][2] + bb0;
                eb[(g + 8) * 68 + o0 + 1] = acc[nt][3] + bb1;
            }
            __syncwarp();

            const int saA = (int)(row0 / 6);
            const int saB = (int)((row0 + 15) / 6);
            for (int sa = saA; sa <= saB; ++sa) {
                if (sa >= n) break;
                const int mb = (int)((long)sa * 6 - row0);   // row index of slot 0
                if (mb >= 0 && mb + 6 <= 16) {
                    // full sample: coalesced float4 path
                    const float* ddp = dd + (size_t)sa * 384;
                    float*       op  = out + (size_t)sa * 384;
#pragma unroll
                    for (int it = 0; it < 3; ++it) {
                        const int f = (it * 32 + lane) * 4;
                        float4 dv = __ldg((const float4*)(ddp + f));
                        float r[4];
#pragma unroll
                        for (int e = 0; e < 4; ++e) {
                            const int fe = f + e;
                            const int o  = fe / 6;
                            const int sl = fe - o * 6;
                            r[e] = eb[(mb + sl) * 68 + o];
                        }
                        float4 ov;
                        ov.x = fmaxf(r[0] + dv.x, 0.f);
                        ov.y = fmaxf(r[1] + dv.y, 0.f);
                        ov.z = fmaxf(r[2] + dv.z, 0.f);
                        ov.w = fmaxf(r[3] + dv.w, 0.f);
                        *(float4*)(op + f) = ov;
                    }
                } else {
                    // boundary sample: scalar path
#pragma unroll
                    for (int sl = 0; sl < 6; ++sl) {
                        const int m = mb + sl;
                        if (m < 0 || m >= 16) continue;
                        if (row0 + m >= rmax) continue;
#pragma unroll
                        for (int h = 0; h < 2; ++h) {
                            const int o = lane + 32 * h;
                            const size_t a = (size_t)sa * 384 + (size_t)o * 6 + sl;
                            out[a] = fmaxf(eb[m * 68 + o] + dd[a], 0.f);
                        }
                    }
                }
            }
            __syncwarp();   // eb reused next tile
        }
    }
}

extern "C" void kernel_launch(void* const* d_in, const int* in_sizes, int n_in,
                              void* d_out, int out_size) {
    const float* x  = (const float*)d_in[0];
    const float* dd = (const float*)d_in[1];
    const float* W1 = (const float*)d_in[2];
    const float* b1 = (const float*)d_in[3];
    const float* W2 = (const float*)d_in[4];
    const float* b2 = (const float*)d_in[5];
    const float* W3 = (const float*)d_in[6];
    const float* b3 = (const float*)d_in[7];
    float* out = (float*)d_out;

    const int n = in_sizes[0] / (ND * 12);

    int sms = 148;
    cudaDeviceGetAttribute(&sms, cudaDevAttrMultiProcessorCount, 0);
    cudaFuncSetAttribute(dijet_mma, cudaFuncAttributeMaxDynamicSharedMemorySize, SMEM_BYTES);

    dijet_mma<<<sms * 2, THREADS, SMEM_BYTES>>>(x, dd, W1, b1, W2, b2, W3, b3, out, n);
}

// round 15
// speedup vs baseline: 1.3511x; 1.2122x over previous
#include <cuda_runtime.h>
#include <cuda_fp16.h>
#include <cstdint>

#define ND 64
#define THREADS 512
#define TILE_R 256           // rows per CTA tile (16 warps x m16)

// ---- smem layout (bytes) ----
#define BF_OFF   0                    // uint4 [3 l][12 j][4 p][32 lane] = 73728
#define BIAS_OFF 73728                // 192 floats = 768
#define EPI_OFF  74496                // 16 warps * 16*68 floats = 69632 (scr overlaps)
#define SMEM_BYTES (74496 + 69632)    // 144128  -> L1D ~84-87 KB

__device__ __forceinline__ uint32_t pk_h(float v0, float v1) {
    __half2 h = __floats2half2_rn(v0, v1);      // single cvt.rn.f16x2.f32
    return *reinterpret_cast<uint32_t*>(&h);
}

__device__ __forceinline__ void mma4(float* c, const uint32_t* a, uint32_t b0, uint32_t b1) {
    asm volatile(
        "mma.sync.aligned.m16n8k16.row.col.f32.f16.f16.f32 "
        "{%0,%1,%2,%3}, {%4,%5,%6,%7}, {%8,%9}, {%0,%1,%2,%3};"
        : "+f"(c[0]), "+f"(c[1]), "+f"(c[2]), "+f"(c[3])
        : "r"(a[0]), "r"(a[1]), "r"(a[2]), "r"(a[3]), "r"(b0), "r"(b1));
}

__device__ __forceinline__ void pf_l2(const void* p) {
    asm volatile("prefetch.global.L2 [%0];" :: "l"(p));
}

__global__ __launch_bounds__(THREADS, 1)
void dijet_mma(const float* __restrict__ x, const float* __restrict__ dd,
               const float* __restrict__ W1, const float* __restrict__ b1,
               const float* __restrict__ W2, const float* __restrict__ b2,
               const float* __restrict__ W3, const float* __restrict__ b3,
               float* __restrict__ out, int n) {
    extern __shared__ char smem[];
    uint4*  Bfr  = (uint4*)(smem + BF_OFF);
    float*  bias = (float*)(smem + BIAS_OFF);
    float*  scr  = (float*)(smem + EPI_OFF);     // staging bounce, overlapped with eb

    const int tid  = threadIdx.x;
    const int w    = tid >> 5;
    const int lane = tid & 31;
    const int g    = lane >> 2;     // row-in-frag 0..7
    const int c    = lane & 3;      // k/n sub-index

    float* eb = (float*)(smem + EPI_OFF) + w * (16 * 68);

    if (tid < 64) { bias[tid] = b1[tid]; bias[64 + tid] = b2[tid]; bias[128 + tid] = b3[tid]; }

    // ==== stage weights once: fp32 [o][i][k] -> single-fp16 fragments ====
    {
        const float* Wg[3] = {W1, W2, W3};
        for (int l = 0; l < 3; ++l) {
            for (int oh = 0; oh < 2; ++oh) {
                __syncthreads();
                const float4* src = (const float4*)(Wg[l] + oh * 32 * 192);
                float4* dst = (float4*)scr;
                for (int i4 = tid; i4 < 1536; i4 += THREADS) dst[i4] = src[i4];
                __syncthreads();
                {
                    int cmb = w;                    // 0..15, use 0..11 (j), 2 p per warp
                    if (cmb < 12) {
                        int j = cmb;
#pragma unroll
                        for (int pp = 0; pp < 2; ++pp) {
                            int p = oh * 2 + pp;
                            int nl0 = pp * 16 + g, nl1 = nl0 + 8;
                            int k0 = j * 16 + 2 * c;
                            int blk = k0 >> 6, i0 = k0 & 63;
                            const float* s0p = scr + nl0 * 192 + blk;
                            const float* s1p = scr + nl1 * 192 + blk;
                            uint32_t h0 = pk_h(s0p[i0 * 3],       s0p[(i0 + 1) * 3]);
                            uint32_t h1 = pk_h(s0p[(i0 + 8) * 3], s0p[(i0 + 9) * 3]);
                            uint32_t h2 = pk_h(s1p[i0 * 3],       s1p[(i0 + 1) * 3]);
                            uint32_t h3 = pk_h(s1p[(i0 + 8) * 3], s1p[(i0 + 9) * 3]);
                            Bfr[((l * 12 + j) * 4 + p) * 32 + lane] = make_uint4(h0, h1, h2, h3);
                        }
                    }
                }
            }
        }
        __syncthreads();   // last barrier: Bfr/bias read-only, scr dead -> eb valid
    }

    const long rmax   = (long)n * 6;
    const int  ntiles = (int)((rmax + TILE_R - 1) / TILE_R);

    for (int tile = blockIdx.x; tile < ntiles; tile += gridDim.x) {
        const long base = (long)tile * TILE_R;
        const long row0 = base + w * 16;           // this warp's first row

        const long r0 = row0 + g;
        const long r1 = r0 + 8;
        const bool v0 = r0 < rmax, v1 = r1 < rmax;
        const int  sa0 = (int)(r0 / 6), sl0 = (int)(r0 - (long)sa0 * 6);
        const int  sa1 = (int)(r1 / 6), sl1 = (int)(r1 - (long)sa1 * 6);

        uint32_t Ahx[8][4], Ahd[4][4];

        // ==== direct gmem gather -> A fragments (all 1-term fp16) ====
        {
            const float* px0 = x + (size_t)sa0 * 768 + 2 * sl0;
            const float* px1 = x + (size_t)sa1 * 768 + 2 * sl1;
            const float2 z2 = make_float2(0.f, 0.f);
#pragma unroll
            for (int j = 0; j < 4; ++j) {
                const int i0 = j * 16 + 2 * c;
                float2 p00 = v0 ? __ldg((const float2*)(px0 + i0 * 12))       : z2;
                float2 p01 = v0 ? __ldg((const float2*)(px0 + (i0 + 1) * 12)) : z2;
                float2 p02 = v0 ? __ldg((const float2*)(px0 + (i0 + 8) * 12)) : z2;
                float2 p03 = v0 ? __ldg((const float2*)(px0 + (i0 + 9) * 12)) : z2;
                float2 p10 = v1 ? __ldg((const float2*)(px1 + i0 * 12))       : z2;
                float2 p11 = v1 ? __ldg((const float2*)(px1 + (i0 + 1) * 12)) : z2;
                float2 p12 = v1 ? __ldg((const float2*)(px1 + (i0 + 8) * 12)) : z2;
                float2 p13 = v1 ? __ldg((const float2*)(px1 + (i0 + 9) * 12)) : z2;
                Ahx[j][0]     = pk_h(p00.x, p01.x);
                Ahx[j][1]     = pk_h(p10.x, p11.x);
                Ahx[j][2]     = pk_h(p02.x, p03.x);
                Ahx[j][3]     = pk_h(p12.x, p13.x);
                Ahx[j + 4][0] = pk_h(p00.y, p01.y);
                Ahx[j + 4][1] = pk_h(p10.y, p11.y);
                Ahx[j + 4][2] = pk_h(p02.y, p03.y);
                Ahx[j + 4][3] = pk_h(p12.y, p13.y);
            }
            const float* d0p = dd + (size_t)sa0 * 384 + sl0;
            const float* d1p = dd + (size_t)sa1 * 384 + sl1;
#pragma unroll
            for (int jd = 0; jd < 4; ++jd) {
                const int i0 = jd * 16 + 2 * c;
                float e00 = v0 ? __ldg(d0p + i0 * 6)       : 0.f;
                float e01 = v0 ? __ldg(d0p + (i0 + 1) * 6) : 0.f;
                float e02 = v0 ? __ldg(d0p + (i0 + 8) * 6) : 0.f;
                float e03 = v0 ? __ldg(d0p + (i0 + 9) * 6) : 0.f;
                float e10 = v1 ? __ldg(d1p + i0 * 6)       : 0.f;
                float e11 = v1 ? __ldg(d1p + (i0 + 1) * 6) : 0.f;
                float e12 = v1 ? __ldg(d1p + (i0 + 8) * 6) : 0.f;
                float e13 = v1 ? __ldg(d1p + (i0 + 9) * 6) : 0.f;
                Ahd[jd][0] = pk_h(e00, e01);
                Ahd[jd][1] = pk_h(e10, e11);
                Ahd[jd][2] = pk_h(e02, e03);
                Ahd[jd][3] = pk_h(e12, e13);
            }
        }

        // ==== L2-prefetch next tile's x and d (hides DRAM latency behind mainloop) ====
        {
            const int nxt = tile + gridDim.x;
            if (nxt < ntiles) {
                const long nbase = (long)nxt * TILE_R;
                const int  ns0 = (int)(nbase / 6);
                const int  ns1 = (int)((nbase + TILE_R - 1) / 6);       // last sample
                const char* xb = (const char*)(x + (size_t)ns0 * 768);
                const char* db = (const char*)(dd + (size_t)ns0 * 384);
                const long xbytes = (long)(ns1 - ns0 + 1) * 3072;       // ~132 KB
                const long dbytes = (long)(ns1 - ns0 + 1) * 1536;       // ~66 KB
                long o0 = (long)tid * 128;
                if (o0 < xbytes)          pf_l2(xb + o0);
                if (o0 + 65536 < xbytes)  pf_l2(xb + o0 + 65536);
                if (o0 + 131072 < xbytes) pf_l2(xb + o0 + 131072);
                if (o0 < dbytes)          pf_l2(db + o0);
                if (o0 + 65536 < dbytes)  pf_l2(db + o0 + 65536);
            }
        }

        float acc[8][4];
#pragma unroll
        for (int nt = 0; nt < 8; ++nt)
#pragma unroll
            for (int e = 0; e < 4; ++e) acc[nt][e] = 0.f;

        // ==== 3 chained layers: all 1-term fp16 ====
#pragma unroll
        for (int l = 0; l < 3; ++l) {
#pragma unroll
            for (int j = 0; j < 8; ++j) {
                const uint4* bp = Bfr + ((l * 12 + j) * 4) * 32 + lane;
#pragma unroll
                for (int p = 0; p < 4; ++p) {
                    uint4 bh = bp[p * 32];
                    mma4(acc[2 * p],     Ahx[j], bh.x, bh.y);
                    mma4(acc[2 * p + 1], Ahx[j], bh.z, bh.w);
                }
            }
#pragma unroll
            for (int jd = 0; jd < 4; ++jd) {
                const uint4* bp = Bfr + ((l * 12 + 8 + jd) * 4) * 32 + lane;
#pragma unroll
                for (int p = 0; p < 4; ++p) {
                    uint4 bh = bp[p * 32];
                    mma4(acc[2 * p],     Ahd[jd], bh.x, bh.y);
                    mma4(acc[2 * p + 1], Ahd[jd], bh.z, bh.w);
                }
            }
            if (l < 2) {
                // D -> next-layer d fragments, register-local (o dim == next k dim)
#pragma unroll
                for (int jd = 0; jd < 4; ++jd) {
                    const int o0 = jd * 16 + 2 * c;
                    float bb0 = bias[l * 64 + o0],     bb1 = bias[l * 64 + o0 + 1];
                    float bb8 = bias[l * 64 + o0 + 8], bb9 = bias[l * 64 + o0 + 9];
                    Ahd[jd][0] = pk_h(fmaxf(acc[2 * jd][0] + bb0, 0.f),
                                      fmaxf(acc[2 * jd][1] + bb1, 0.f));
                    Ahd[jd][1] = pk_h(fmaxf(acc[2 * jd][2] + bb0, 0.f),
                                      fmaxf(acc[2 * jd][3] + bb1, 0.f));
                    Ahd[jd][2] = pk_h(fmaxf(acc[2 * jd + 1][0] + bb8, 0.f),
                                      fmaxf(acc[2 * jd + 1][1] + bb9, 0.f));
                    Ahd[jd][3] = pk_h(fmaxf(acc[2 * jd + 1][2] + bb8, 0.f),
                                      fmaxf(acc[2 * jd + 1][3] + bb9, 0.f));
#pragma unroll
                    for (int e = 0; e < 4; ++e) {
                        acc[2 * jd][e] = 0.f;
                        acc[2 * jd + 1][e] = 0.f;
                    }
                }
            }
        }

        // ==== epilogue: acc+b3 -> warp smem transpose -> relu(+d1) -> gmem ====
        {
#pragma unroll
            for (int nt = 0; nt < 8; ++nt) {
                const int o0 = nt * 8 + 2 * c;
                const float bb0 = bias[128 + o0], bb1 = bias[128 + o0 + 1];
                *(float2*)(eb + g * 68 + o0) =
                    make_float2(acc[nt][0] + bb0, acc[nt][1] + bb1);
                *(float2*)(eb + (g + 8) * 68 + o0) =
                    make_float2(acc[nt][2] + bb0, acc[nt][3] + bb1);
            }
            __syncwarp();

            const int saA = (int)(row0 / 6);
            const int saB = (int)((row0 + 15) / 6);
            for (int sa = saA; sa <= saB; ++sa) {
                if (sa >= n) break;
                const int mb = (int)((long)sa * 6 - row0);   // row index of slot 0
                if (mb >= 0 && mb + 6 <= 16) {
                    // full sample: coalesced float4 path
                    const float* ddp = dd + (size_t)sa * 384;
                    float*       op  = out + (size_t)sa * 384;
#pragma unroll
                    for (int it = 0; it < 3; ++it) {
                        const int f = (it * 32 + lane) * 4;
                        float4 dv = __ldg((const float4*)(ddp + f));
                        float r[4];
#pragma unroll
                        for (int e = 0; e < 4; ++e) {
                            const int fe = f + e;
                            const int o  = fe / 6;
                            const int sl = fe - o * 6;
                            r[e] = eb[(mb + sl) * 68 + o];
                        }
                        float4 ov;
                        ov.x = fmaxf(r[0] + dv.x, 0.f);
                        ov.y = fmaxf(r[1] + dv.y, 0.f);
                        ov.z = fmaxf(r[2] + dv.z, 0.f);
                        ov.w = fmaxf(r[3] + dv.w, 0.f);
                        *(float4*)(op + f) = ov;
                    }
                } else {
                    // boundary sample: scalar path
#pragma unroll
                    for (int sl = 0; sl < 6; ++sl) {
                        const int m = mb + sl;
                        if (m < 0 || m >= 16) continue;
                        if (row0 + m >= rmax) continue;
#pragma unroll
                        for (int h = 0; h < 2; ++h) {
                            const int o = lane + 32 * h;
                            const size_t a = (size_t)sa * 384 + (size_t)o * 6 + sl;
                            out[a] = fmaxf(eb[m * 68 + o] + dd[a], 0.f);
                        }
                    }
                }
            }
            __syncwarp();   // eb reused next tile
        }
    }
}

extern "C" void kernel_launch(void* const* d_in, const int* in_sizes, int n_in,
                              void* d_out, int out_size) {
    const float* x  = (const float*)d_in[0];
    const float* dd = (const float*)d_in[1];
    const float* W1 = (const float*)d_in[2];
    const float* b1 = (const float*)d_in[3];
    const float* W2 = (const float*)d_in[4];
    const float* b2 = (const float*)d_in[5];
    const float* W3 = (const float*)d_in[6];
    const float* b3 = (const float*)d_in[7];
    float* out = (float*)d_out;

    const int n = in_sizes[0] / (ND * 12);

    int sms = 148;
    cudaDeviceGetAttribute(&sms, cudaDevAttrMultiProcessorCount, 0);
    cudaFuncSetAttribute(dijet_mma, cudaFuncAttributeMaxDynamicSharedMemorySize, SMEM_BYTES);

    dijet_mma<<<sms, THREADS, SMEM_BYTES>>>(x, dd, W1, b1, W2, b2, W3, b3, out, n);
}

// round 16
// speedup vs baseline: 1.3746x; 1.0174x over previous
#include <cuda_runtime.h>
#include <cuda_fp16.h>
#include <cstdint>

#define ND 64
#define THREADS 512
#define TILE_R 256           // rows per CTA tile (16 warps x m16)

// ---- smem layout (bytes) ----
#define BF_OFF   0                    // uint4 [3 l][12 j][4 p][32 lane] = 73728
#define BIAS_OFF 73728                // 192 floats = 768
#define EPI_OFF  74496                // 16 warps * 16*68 floats = 69632 (scr overlaps)
#define SMEM_BYTES (74496 + 69632)    // 144128  -> L1D ~84-87 KB

__device__ __forceinline__ uint32_t pk_h(float v0, float v1) {
    __half2 h = __floats2half2_rn(v0, v1);      // single cvt.rn.f16x2.f32
    return *reinterpret_cast<uint32_t*>(&h);
}

__device__ __forceinline__ void mma4(float* c, const uint32_t* a, uint32_t b0, uint32_t b1) {
    asm volatile(
        "mma.sync.aligned.m16n8k16.row.col.f32.f16.f16.f32 "
        "{%0,%1,%2,%3}, {%4,%5,%6,%7}, {%8,%9}, {%0,%1,%2,%3};"
        : "+f"(c[0]), "+f"(c[1]), "+f"(c[2]), "+f"(c[3])
        : "r"(a[0]), "r"(a[1]), "r"(a[2]), "r"(a[3]), "r"(b0), "r"(b1));
}

__device__ __forceinline__ void pf_l2(const void* p) {
    asm volatile("prefetch.global.L2 [%0];" :: "l"(p));
}

__global__ __launch_bounds__(THREADS, 1)
void dijet_mma(const float* __restrict__ x, const float* __restrict__ dd,
               const float* __restrict__ W1, const float* __restrict__ b1,
               const float* __restrict__ W2, const float* __restrict__ b2,
               const float* __restrict__ W3, const float* __restrict__ b3,
               float* __restrict__ out, int n) {
    extern __shared__ char smem[];
    uint4*  Bfr  = (uint4*)(smem + BF_OFF);
    float*  bias = (float*)(smem + BIAS_OFF);
    float*  scr  = (float*)(smem + EPI_OFF);     // staging bounce, overlapped with eb

    const int tid  = threadIdx.x;
    const int w    = tid >> 5;
    const int lane = tid & 31;
    const int g    = lane >> 2;     // row-in-frag 0..7
    const int c    = lane & 3;      // k/n sub-index

    float* eb = (float*)(smem + EPI_OFF) + w * (16 * 68);

    if (tid < 64) { bias[tid] = b1[tid]; bias[64 + tid] = b2[tid]; bias[128 + tid] = b3[tid]; }

    // ==== stage weights once: fp32 [o][i][k] -> single-fp16 fragments ====
    {
        const float* Wg[3] = {W1, W2, W3};
        for (int l = 0; l < 3; ++l) {
            for (int oh = 0; oh < 2; ++oh) {
                __syncthreads();
                const float4* src = (const float4*)(Wg[l] + oh * 32 * 192);
                float4* dst = (float4*)scr;
                for (int i4 = tid; i4 < 1536; i4 += THREADS) dst[i4] = src[i4];
                __syncthreads();
                {
                    int cmb = w;                    // 0..15, use 0..11 (j), 2 p per warp
                    if (cmb < 12) {
                        int j = cmb;
#pragma unroll
                        for (int pp = 0; pp < 2; ++pp) {
                            int p = oh * 2 + pp;
                            int nl0 = pp * 16 + g, nl1 = nl0 + 8;
                            int k0 = j * 16 + 2 * c;
                            int blk = k0 >> 6, i0 = k0 & 63;
                            const float* s0p = scr + nl0 * 192 + blk;
                            const float* s1p = scr + nl1 * 192 + blk;
                            uint32_t h0 = pk_h(s0p[i0 * 3],       s0p[(i0 + 1) * 3]);
                            uint32_t h1 = pk_h(s0p[(i0 + 8) * 3], s0p[(i0 + 9) * 3]);
                            uint32_t h2 = pk_h(s1p[i0 * 3],       s1p[(i0 + 1) * 3]);
                            uint32_t h3 = pk_h(s1p[(i0 + 8) * 3], s1p[(i0 + 9) * 3]);
                            Bfr[((l * 12 + j) * 4 + p) * 32 + lane] = make_uint4(h0, h1, h2, h3);
                        }
                    }
                }
            }
        }
        __syncthreads();   // last barrier: Bfr/bias read-only, scr dead -> eb valid
    }

    const long rmax   = (long)n * 6;
    const int  ntiles = (int)((rmax + TILE_R - 1) / TILE_R);

    for (int tile = blockIdx.x; tile < ntiles; tile += gridDim.x) {
        const long base = (long)tile * TILE_R;
        const long row0 = base + w * 16;           // this warp's first row

        const long r0 = row0 + g;
        const long r1 = r0 + 8;
        const bool v0 = r0 < rmax, v1 = r1 < rmax;
        const int  sa0 = (int)(r0 / 6), sl0 = (int)(r0 - (long)sa0 * 6);
        const int  sa1 = (int)(r1 / 6), sl1 = (int)(r1 - (long)sa1 * 6);

        uint32_t Ahx[8][4], Ahd[4][4];

        // ==== direct gmem gather -> A fragments (all 1-term fp16) ====
        {
            const float* px0 = x + (size_t)sa0 * 768 + 2 * sl0;
            const float* px1 = x + (size_t)sa1 * 768 + 2 * sl1;
            const float2 z2 = make_float2(0.f, 0.f);
#pragma unroll
            for (int j = 0; j < 4; ++j) {
                const int i0 = j * 16 + 2 * c;
                float2 p00 = v0 ? __ldg((const float2*)(px0 + i0 * 12))       : z2;
                float2 p01 = v0 ? __ldg((const float2*)(px0 + (i0 + 1) * 12)) : z2;
                float2 p02 = v0 ? __ldg((const float2*)(px0 + (i0 + 8) * 12)) : z2;
                float2 p03 = v0 ? __ldg((const float2*)(px0 + (i0 + 9) * 12)) : z2;
                float2 p10 = v1 ? __ldg((const float2*)(px1 + i0 * 12))       : z2;
                float2 p11 = v1 ? __ldg((const float2*)(px1 + (i0 + 1) * 12)) : z2;
                float2 p12 = v1 ? __ldg((const float2*)(px1 + (i0 + 8) * 12)) : z2;
                float2 p13 = v1 ? __ldg((const float2*)(px1 + (i0 + 9) * 12)) : z2;
                Ahx[j][0]     = pk_h(p00.x, p01.x);
                Ahx[j][1]     = pk_h(p10.x, p11.x);
                Ahx[j][2]     = pk_h(p02.x, p03.x);
                Ahx[j][3]     = pk_h(p12.x, p13.x);
                Ahx[j + 4][0] = pk_h(p00.y, p01.y);
                Ahx[j + 4][1] = pk_h(p10.y, p11.y);
                Ahx[j + 4][2] = pk_h(p02.y, p03.y);
                Ahx[j + 4][3] = pk_h(p12.y, p13.y);
            }
            const float* d0p = dd + (size_t)sa0 * 384 + sl0;
            const float* d1p = dd + (size_t)sa1 * 384 + sl1;
#pragma unroll
            for (int jd = 0; jd < 4; ++jd) {
                const int i0 = jd * 16 + 2 * c;
                float e00 = v0 ? __ldg(d0p + i0 * 6)       : 0.f;
                float e01 = v0 ? __ldg(d0p + (i0 + 1) * 6) : 0.f;
                float e02 = v0 ? __ldg(d0p + (i0 + 8) * 6) : 0.f;
                float e03 = v0 ? __ldg(d0p + (i0 + 9) * 6) : 0.f;
                float e10 = v1 ? __ldg(d1p + i0 * 6)       : 0.f;
                float e11 = v1 ? __ldg(d1p + (i0 + 1) * 6) : 0.f;
                float e12 = v1 ? __ldg(d1p + (i0 + 8) * 6) : 0.f;
                float e13 = v1 ? __ldg(d1p + (i0 + 9) * 6) : 0.f;
                Ahd[jd][0] = pk_h(e00, e01);
                Ahd[jd][1] = pk_h(e10, e11);
                Ahd[jd][2] = pk_h(e02, e03);
                Ahd[jd][3] = pk_h(e12, e13);
            }
        }

        // ==== L2-prefetch next tile's x and d (hides DRAM latency behind mainloop) ====
        {
            const int nxt = tile + gridDim.x;
            if (nxt < ntiles) {
                const long nbase = (long)nxt * TILE_R;
                const int  ns0 = (int)(nbase / 6);
                const int  ns1 = (int)((nbase + TILE_R - 1) / 6);       // last sample
                const char* xb = (const char*)(x + (size_t)ns0 * 768);
                const char* db = (const char*)(dd + (size_t)ns0 * 384);
                const long xbytes = (long)(ns1 - ns0 + 1) * 3072;       // ~132 KB
                const long dbytes = (long)(ns1 - ns0 + 1) * 1536;       // ~66 KB
                long o0 = (long)tid * 128;
                if (o0 < xbytes)          pf_l2(xb + o0);
                if (o0 + 65536 < xbytes)  pf_l2(xb + o0 + 65536);
                if (o0 + 131072 < xbytes) pf_l2(xb + o0 + 131072);
                if (o0 < dbytes)          pf_l2(db + o0);
                if (o0 + 65536 < dbytes)  pf_l2(db + o0 + 65536);
            }
        }

        float acc[8][4];
#pragma unroll
        for (int nt = 0; nt < 8; ++nt)
#pragma unroll
            for (int e = 0; e < 4; ++e) acc[nt][e] = 0.f;

        // ==== 3 chained layers: all 1-term fp16 ====
#pragma unroll
        for (int l = 0; l < 3; ++l) {
#pragma unroll
            for (int j = 0; j < 8; ++j) {
                const uint4* bp = Bfr + ((l * 12 + j) * 4) * 32 + lane;
#pragma unroll
                for (int p = 0; p < 4; ++p) {
                    uint4 bh = bp[p * 32];
                    mma4(acc[2 * p],     Ahx[j], bh.x, bh.y);
                    mma4(acc[2 * p + 1], Ahx[j], bh.z, bh.w);
                }
            }
#pragma unroll
            for (int jd = 0; jd < 4; ++jd) {
                const uint4* bp = Bfr + ((l * 12 + 8 + jd) * 4) * 32 + lane;
#pragma unroll
                for (int p = 0; p < 4; ++p) {
                    uint4 bh = bp[p * 32];
                    mma4(acc[2 * p],     Ahd[jd], bh.x, bh.y);
                    mma4(acc[2 * p + 1], Ahd[jd], bh.z, bh.w);
                }
            }
            if (l < 2) {
                // D -> next-layer d fragments, register-local (o dim == next k dim)
#pragma unroll
                for (int jd = 0; jd < 4; ++jd) {
                    const int o0 = jd * 16 + 2 * c;
                    float bb0 = bias[l * 64 + o0],     bb1 = bias[l * 64 + o0 + 1];
                    float bb8 = bias[l * 64 + o0 + 8], bb9 = bias[l * 64 + o0 + 9];
                    Ahd[jd][0] = pk_h(fmaxf(acc[2 * jd][0] + bb0, 0.f),
                                      fmaxf(acc[2 * jd][1] + bb1, 0.f));
                    Ahd[jd][1] = pk_h(fmaxf(acc[2 * jd][2] + bb0, 0.f),
                                      fmaxf(acc[2 * jd][3] + bb1, 0.f));
                    Ahd[jd][2] = pk_h(fmaxf(acc[2 * jd + 1][0] + bb8, 0.f),
                                      fmaxf(acc[2 * jd + 1][1] + bb9, 0.f));
                    Ahd[jd][3] = pk_h(fmaxf(acc[2 * jd + 1][2] + bb8, 0.f),
                                      fmaxf(acc[2 * jd + 1][3] + bb9, 0.f));
#pragma unroll
                    for (int e = 0; e < 4; ++e) {
                        acc[2 * jd][e] = 0.f;
                        acc[2 * jd + 1][e] = 0.f;
                    }
                }
            }
        }

        // ==== epilogue: acc+b3 -> warp smem transpose -> relu(+d1) -> gmem ====
        {
#pragma unroll
            for (int nt = 0; nt < 8; ++nt) {
                const int o0 = nt * 8 + 2 * c;
                const float bb0 = bias[128 + o0], bb1 = bias[128 + o0 + 1];
                *(float2*)(eb + g * 68 + o0) =
                    make_float2(acc[nt][0] + bb0, acc[nt][1] + bb1);
                *(float2*)(eb + (g + 8) * 68 + o0) =
                    make_float2(acc[nt][2] + bb0, acc[nt][3] + bb1);
            }
            __syncwarp();

            const int saA = (int)(row0 / 6);
            const int saB = (int)((row0 + 15) / 6);
            for (int sa = saA; sa <= saB; ++sa) {
                if (sa >= n) break;
                const int mb = (int)((long)sa * 6 - row0);   // row index of slot 0
                if (mb >= 0 && mb + 6 <= 16) {
                    // full sample: coalesced float4 path
                    const float* ddp = dd + (size_t)sa * 384;
                    float*       op  = out + (size_t)sa * 384;
#pragma unroll
                    for (int it = 0; it < 3; ++it) {
                        const int f = (it * 32 + lane) * 4;
                        float4 dv = __ldg((const float4*)(ddp + f));
                        float r[4];
#pragma unroll
                        for (int e = 0; e < 4; ++e) {
                            const int fe = f + e;
                            const int o  = fe / 6;
                            const int sl = fe - o * 6;
                            r[e] = eb[(mb + sl) * 68 + o];
                        }
                        float4 ov;
                        ov.x = fmaxf(r[0] + dv.x, 0.f);
                        ov.y = fmaxf(r[1] + dv.y, 0.f);
                        ov.z = fmaxf(r[2] + dv.z, 0.f);
                        ov.w = fmaxf(r[3] + dv.w, 0.f);
                        *(float4*)(op + f) = ov;
                    }
                } else {
                    // boundary sample: scalar path
#pragma unroll
                    for (int sl = 0; sl < 6; ++sl) {
                        const int m = mb + sl;
                        if (m < 0 || m >= 16) continue;
                        if (row0 + m >= rmax) continue;
#pragma unroll
                        for (int h = 0; h < 2; ++h) {
                            const int o = lane + 32 * h;
                            const size_t a = (size_t)sa * 384 + (size_t)o * 6 + sl;
                            out[a] = fmaxf(eb[m * 68 + o] + dd[a], 0.f);
                        }
                    }
                }
            }
            __syncwarp();   // eb reused next tile
        }
    }
}

extern "C" void kernel_launch(void* const* d_in, const int* in_sizes, int n_in,
                              void* d_out, int out_size) {
    const float* x  = (const float*)d_in[0];
    const float* dd = (const float*)d_in[1];
    const float* W1 = (const float*)d_in[2];
    const float* b1 = (const float*)d_in[3];
    const float* W2 = (const float*)d_in[4];
    const float* b2 = (const float*)d_in[5];
    const float* W3 = (const float*)d_in[6];
    const float* b3 = (const float*)d_in[7];
    float* out = (float*)d_out;

    const int n = in_sizes[0] / (ND * 12);

    int sms = 148;
    cudaDeviceGetAttribute(&sms, cudaDevAttrMultiProcessorCount, 0);
    cudaFuncSetAttribute(dijet_mma, cudaFuncAttributeMaxDynamicSharedMemorySize, SMEM_BYTES);

    dijet_mma<<<sms, THREADS, SMEM_BYTES>>>(x, dd, W1, b1, W2, b2, W3, b3, out, n);
}

// round 17
// speedup vs baseline: 1.3814x; 1.0050x over previous
#include <cuda_runtime.h>
#include <cuda_fp16.h>
#include <cstdint>

#define ND 64
#define THREADS 512
#define TILE_R 256           // rows per CTA tile (16 warps x m16)

// ---- smem layout (bytes) ----
#define BF_OFF   0                    // uint4 [3 l][12 j][4 p][32 lane] = 73728
#define BIAS_OFF 73728                // 192 floats = 768
#define EPI_OFF  74496                // 16 warps * 16*68 floats = 69632 (scr overlaps)
#define SMEM_BYTES (74496 + 69632)    // 144128  -> L1D ~84-87 KB

__device__ __forceinline__ uint32_t pk_h(float v0, float v1) {
    __half2 h = __floats2half2_rn(v0, v1);      // single cvt.rn.f16x2.f32
    return *reinterpret_cast<uint32_t*>(&h);
}

__device__ __forceinline__ void mma4(float* c, const uint32_t* a, uint32_t b0, uint32_t b1) {
    asm volatile(
        "mma.sync.aligned.m16n8k16.row.col.f32.f16.f16.f32 "
        "{%0,%1,%2,%3}, {%4,%5,%6,%7}, {%8,%9}, {%0,%1,%2,%3};"
        : "+f"(c[0]), "+f"(c[1]), "+f"(c[2]), "+f"(c[3])
        : "r"(a[0]), "r"(a[1]), "r"(a[2]), "r"(a[3]), "r"(b0), "r"(b1));
}

__device__ __forceinline__ void pf_l2(const void* p) {
    asm volatile("prefetch.global.L2 [%0];" :: "l"(p));
}

__global__ __launch_bounds__(THREADS, 1)
void dijet_mma(const float* __restrict__ x, const float* __restrict__ dd,
               const float* __restrict__ W1, const float* __restrict__ b1,
               const float* __restrict__ W2, const float* __restrict__ b2,
               const float* __restrict__ W3, const float* __restrict__ b3,
               float* __restrict__ out, int n) {
    extern __shared__ char smem[];
    uint4*  Bfr  = (uint4*)(smem + BF_OFF);
    float*  bias = (float*)(smem + BIAS_OFF);
    float*  scr  = (float*)(smem + EPI_OFF);     // staging bounce, overlapped with eb

    const int tid  = threadIdx.x;
    const int w    = tid >> 5;
    const int lane = tid & 31;
    const int g    = lane >> 2;     // row-in-frag 0..7
    const int c    = lane & 3;      // k/n sub-index

    float* eb = (float*)(smem + EPI_OFF) + w * (16 * 68);

    if (tid < 64) { bias[tid] = b1[tid]; bias[64 + tid] = b2[tid]; bias[128 + tid] = b3[tid]; }

    // ==== stage weights once: fp32 [o][i][k] -> single-fp16 fragments ====
    {
        const float* Wg[3] = {W1, W2, W3};
        for (int l = 0; l < 3; ++l) {
            for (int oh = 0; oh < 2; ++oh) {
                __syncthreads();
                const float4* src = (const float4*)(Wg[l] + oh * 32 * 192);
                float4* dst = (float4*)scr;
                for (int i4 = tid; i4 < 1536; i4 += THREADS) dst[i4] = src[i4];
                __syncthreads();
                {
                    int cmb = w;                    // 0..15, use 0..11 (j), 2 p per warp
                    if (cmb < 12) {
                        int j = cmb;
#pragma unroll
                        for (int pp = 0; pp < 2; ++pp) {
                            int p = oh * 2 + pp;
                            int nl0 = pp * 16 + g, nl1 = nl0 + 8;
                            int k0 = j * 16 + 2 * c;
                            int blk = k0 >> 6, i0 = k0 & 63;
                            const float* s0p = scr + nl0 * 192 + blk;
                            const float* s1p = scr + nl1 * 192 + blk;
                            uint32_t h0 = pk_h(s0p[i0 * 3],       s0p[(i0 + 1) * 3]);
                            uint32_t h1 = pk_h(s0p[(i0 + 8) * 3], s0p[(i0 + 9) * 3]);
                            uint32_t h2 = pk_h(s1p[i0 * 3],       s1p[(i0 + 1) * 3]);
                            uint32_t h3 = pk_h(s1p[(i0 + 8) * 3], s1p[(i0 + 9) * 3]);
                            Bfr[((l * 12 + j) * 4 + p) * 32 + lane] = make_uint4(h0, h1, h2, h3);
                        }
                    }
                }
            }
        }
        __syncthreads();   // last barrier: Bfr/bias read-only, scr dead -> eb valid
    }

    const long rmax   = (long)n * 6;
    const int  ntiles = (int)((rmax + TILE_R - 1) / TILE_R);

    for (int tile = blockIdx.x; tile < ntiles; tile += gridDim.x) {
        const long base = (long)tile * TILE_R;
        const long row0 = base + w * 16;           // this warp's first row

        // clamped addressing: out-of-range rows read valid (garbage) data,
        // compute garbage accs, and are never written (epilogue guards).
        const long r0 = row0 + g;
        const long r1 = r0 + 8;
        const int  sa0 = (int)min(r0 / 6, (long)(n - 1));
        const int  sa1 = (int)min(r1 / 6, (long)(n - 1));
        const int  sl0 = (int)(r0 - (r0 / 6) * 6);
        const int  sl1 = (int)(r1 - (r1 / 6) * 6);

        uint32_t Ahx[8][4], Ahd[4][4];

        // ==== direct gmem gather -> A fragments (all 1-term fp16) ====
        {
            const float* px0 = x + (size_t)sa0 * 768 + 2 * sl0;
            const float* px1 = x + (size_t)sa1 * 768 + 2 * sl1;
#pragma unroll
            for (int j = 0; j < 4; ++j) {
                const int i0 = j * 16 + 2 * c;
                float2 p00 = __ldg((const float2*)(px0 + i0 * 12));
                float2 p01 = __ldg((const float2*)(px0 + (i0 + 1) * 12));
                float2 p02 = __ldg((const float2*)(px0 + (i0 + 8) * 12));
                float2 p03 = __ldg((const float2*)(px0 + (i0 + 9) * 12));
                float2 p10 = __ldg((const float2*)(px1 + i0 * 12));
                float2 p11 = __ldg((const float2*)(px1 + (i0 + 1) * 12));
                float2 p12 = __ldg((const float2*)(px1 + (i0 + 8) * 12));
                float2 p13 = __ldg((const float2*)(px1 + (i0 + 9) * 12));
                Ahx[j][0]     = pk_h(p00.x, p01.x);
                Ahx[j][1]     = pk_h(p10.x, p11.x);
                Ahx[j][2]     = pk_h(p02.x, p03.x);
                Ahx[j][3]     = pk_h(p12.x, p13.x);
                Ahx[j + 4][0] = pk_h(p00.y, p01.y);
                Ahx[j + 4][1] = pk_h(p10.y, p11.y);
                Ahx[j + 4][2] = pk_h(p02.y, p03.y);
                Ahx[j + 4][3] = pk_h(p12.y, p13.y);
            }
            const float* d0p = dd + (size_t)sa0 * 384 + sl0;
            const float* d1p = dd + (size_t)sa1 * 384 + sl1;
#pragma unroll
            for (int jd = 0; jd < 4; ++jd) {
                const int i0 = jd * 16 + 2 * c;
                float e00 = __ldg(d0p + i0 * 6);
                float e01 = __ldg(d0p + (i0 + 1) * 6);
                float e02 = __ldg(d0p + (i0 + 8) * 6);
                float e03 = __ldg(d0p + (i0 + 9) * 6);
                float e10 = __ldg(d1p + i0 * 6);
                float e11 = __ldg(d1p + (i0 + 1) * 6);
                float e12 = __ldg(d1p + (i0 + 8) * 6);
                float e13 = __ldg(d1p + (i0 + 9) * 6);
                Ahd[jd][0] = pk_h(e00, e01);
                Ahd[jd][1] = pk_h(e10, e11);
                Ahd[jd][2] = pk_h(e02, e03);
                Ahd[jd][3] = pk_h(e12, e13);
            }
        }

        // ==== L2-prefetch next tile's x and d (hides DRAM latency behind mainloop) ====
        {
            const int nxt = tile + gridDim.x;
            if (nxt < ntiles) {
                const long nbase = (long)nxt * TILE_R;
                const int  ns0 = (int)(nbase / 6);
                const int  ns1 = (int)((nbase + TILE_R - 1) / 6);       // last sample
                const char* xb = (const char*)(x + (size_t)ns0 * 768);
                const char* db = (const char*)(dd + (size_t)ns0 * 384);
                const long xbytes = (long)(ns1 - ns0 + 1) * 3072;       // ~132 KB
                const long dbytes = (long)(ns1 - ns0 + 1) * 1536;       // ~66 KB
                long o0 = (long)tid * 128;
                if (o0 < xbytes)          pf_l2(xb + o0);
                if (o0 + 65536 < xbytes)  pf_l2(xb + o0 + 65536);
                if (o0 + 131072 < xbytes) pf_l2(xb + o0 + 131072);
                if (o0 < dbytes)          pf_l2(db + o0);
                if (o0 + 65536 < dbytes)  pf_l2(db + o0 + 65536);
            }
        }

        float acc[8][4];
#pragma unroll
        for (int nt = 0; nt < 8; ++nt)
#pragma unroll
            for (int e = 0; e < 4; ++e) acc[nt][e] = 0.f;

        // ==== 3 chained layers: all 1-term fp16 ====
#pragma unroll
        for (int l = 0; l < 3; ++l) {
#pragma unroll
            for (int j = 0; j < 8; ++j) {
                const uint4* bp = Bfr + ((l * 12 + j) * 4) * 32 + lane;
#pragma unroll
                for (int p = 0; p < 4; ++p) {
                    uint4 bh = bp[p * 32];
                    mma4(acc[2 * p],     Ahx[j], bh.x, bh.y);
                    mma4(acc[2 * p + 1], Ahx[j], bh.z, bh.w);
                }
            }
#pragma unroll
            for (int jd = 0; jd < 4; ++jd) {
                const uint4* bp = Bfr + ((l * 12 + 8 + jd) * 4) * 32 + lane;
#pragma unroll
                for (int p = 0; p < 4; ++p) {
                    uint4 bh = bp[p * 32];
                    mma4(acc[2 * p],     Ahd[jd], bh.x, bh.y);
                    mma4(acc[2 * p + 1], Ahd[jd], bh.z, bh.w);
                }
            }
            if (l < 2) {
                // D -> next-layer d fragments, register-local (o dim == next k dim)
#pragma unroll
                for (int jd = 0; jd < 4; ++jd) {
                    const int o0 = jd * 16 + 2 * c;
                    float bb0 = bias[l * 64 + o0],     bb1 = bias[l * 64 + o0 + 1];
                    float bb8 = bias[l * 64 + o0 + 8], bb9 = bias[l * 64 + o0 + 9];
                    Ahd[jd][0] = pk_h(fmaxf(acc[2 * jd][0] + bb0, 0.f),
                                      fmaxf(acc[2 * jd][1] + bb1, 0.f));
                    Ahd[jd][1] = pk_h(fmaxf(acc[2 * jd][2] + bb0, 0.f),
                                      fmaxf(acc[2 * jd][3] + bb1, 0.f));
                    Ahd[jd][2] = pk_h(fmaxf(acc[2 * jd + 1][0] + bb8, 0.f),
                                      fmaxf(acc[2 * jd + 1][1] + bb9, 0.f));
                    Ahd[jd][3] = pk_h(fmaxf(acc[2 * jd + 1][2] + bb8, 0.f),
                                      fmaxf(acc[2 * jd + 1][3] + bb9, 0.f));
#pragma unroll
                    for (int e = 0; e < 4; ++e) {
                        acc[2 * jd][e] = 0.f;
                        acc[2 * jd + 1][e] = 0.f;
                    }
                }
            }
        }

        // ==== epilogue: acc+b3 -> warp smem transpose -> relu(+d1) -> gmem (.cs) ====
        {
#pragma unroll
            for (int nt = 0; nt < 8; ++nt) {
                const int o0 = nt * 8 + 2 * c;
                const float bb0 = bias[128 + o0], bb1 = bias[128 + o0 + 1];
                *(float2*)(eb + g * 68 + o0) =
                    make_float2(acc[nt][0] + bb0, acc[nt][1] + bb1);
                *(float2*)(eb + (g + 8) * 68 + o0) =
                    make_float2(acc[nt][2] + bb0, acc[nt][3] + bb1);
            }
            __syncwarp();

            const int saA = (int)(row0 / 6);
            const int saB = (int)((row0 + 15) / 6);
            for (int sa = saA; sa <= saB; ++sa) {
                if (sa >= n) break;
                const int mb = (int)((long)sa * 6 - row0);   // row index of slot 0
                if (mb >= 0 && mb + 6 <= 16) {
                    // full sample: coalesced float4 path, streaming stores
                    const float* ddp = dd + (size_t)sa * 384;
                    float*       op  = out + (size_t)sa * 384;
#pragma unroll
                    for (int it = 0; it < 3; ++it) {
                        const int f = (it * 32 + lane) * 4;
                        float4 dv = __ldg((const float4*)(ddp + f));
                        float r[4];
#pragma unroll
                        for (int e = 0; e < 4; ++e) {
                            const int fe = f + e;
                            const int o  = fe / 6;
                            const int sl = fe - o * 6;
                            r[e] = eb[(mb + sl) * 68 + o];
                        }
                        float4 ov;
                        ov.x = fmaxf(r[0] + dv.x, 0.f);
                        ov.y = fmaxf(r[1] + dv.y, 0.f);
                        ov.z = fmaxf(r[2] + dv.z, 0.f);
                        ov.w = fmaxf(r[3] + dv.w, 0.f);
                        __stcs((float4*)(op + f), ov);
                    }
                } else {
                    // boundary sample: scalar path
#pragma unroll
                    for (int sl = 0; sl < 6; ++sl) {
                        const int m = mb + sl;
                        if (m < 0 || m >= 16) continue;
                        if (row0 + m >= rmax) continue;
#pragma unroll
                        for (int h = 0; h < 2; ++h) {
                            const int o = lane + 32 * h;
                            const size_t a = (size_t)sa * 384 + (size_t)o * 6 + sl;
                            __stcs(out + a, fmaxf(eb[m * 68 + o] + __ldg(dd + a), 0.f));
                        }
                    }
                }
            }
            __syncwarp();   // eb reused next tile
        }
    }
}

extern "C" void kernel_launch(void* const* d_in, const int* in_sizes, int n_in,
                              void* d_out, int out_size) {
    const float* x  = (const float*)d_in[0];
    const float* dd = (const float*)d_in[1];
    const float* W1 = (const float*)d_in[2];
    const float* b1 = (const float*)d_in[3];
    const float* W2 = (const float*)d_in[4];
    const float* b2 = (const float*)d_in[5];
    const float* W3 = (const float*)d_in[6];
    const float* b3 = (const float*)d_in[7];
    float* out = (float*)d_out;

    const int n = in_sizes[0] / (ND * 12);

    int sms = 148;
    cudaDeviceGetAttribute(&sms, cudaDevAttrMultiProcessorCount, 0);
    cudaFuncSetAttribute(dijet_mma, cudaFuncAttributeMaxDynamicSharedMemorySize, SMEM_BYTES);

    dijet_mma<<<sms, THREADS, SMEM_BYTES>>>(x, dd, W1, b1, W2, b2, W3, b3, out, n);
}